// round 10
// baseline (speedup 1.0000x reference)
#include <cuda_runtime.h>
#include <math.h>

#define NN 100000
#define EE 1000000
#define NB1 98     // ceil(NN/1024)
#define GL  444    // grid for fused layer kernel (3 blocks/SM)

typedef unsigned long long ull;

// ---------------- scratch (static device globals; no allocation) -------------
__device__ float  g_bufA[(size_t)NN*64];   // layer output ping
__device__ float  g_bufB[(size_t)NN*64];   // layer output pong
__device__ float  g_as[NN*2];              // per-node src scores
__device__ float4 g_att[NN];               // (as0, as1, ad0, ad1) per node
__device__ int    g_deg[NN];               // zero-init; re-zeroed by k_scatter
__device__ int    g_off[NN];
__device__ int    g_cursor[NN];
__device__ int    g_esrc[EE];
__device__ int    g_bsum[128];
__device__ float  g_part[592*128];         // BN partials per block
__device__ float  g_bnscale[64];
__device__ float  g_bnshift[64];
__device__ int    g_bncnt;

__device__ __forceinline__ float lrelu(float v){ return v > 0.f ? v : 0.2f*v; }

__device__ __forceinline__ void upk2(float& lo, float& hi, ull u){
  asm("mov.b64 {%0, %1}, %2;" : "=f"(lo), "=f"(hi) : "l"(u));
}
#define FMA2(d, a, b, c) \
  asm("fma.rn.f32x2 %0, %1, %2, %3;" : "=l"(d) : "l"(a), "l"(b), "l"(c))

// ---------------- CSR build --------------------------------------------------
__global__ void k_count(const int* __restrict__ ei){
  int e = blockIdx.x*blockDim.x + threadIdx.x;
  if (e < EE) atomicAdd(&g_deg[ei[EE + e]], 1);
}

__global__ void k_scan1(){
  __shared__ int s[256];
  int tid = threadIdx.x;
  int base = blockIdx.x*1024 + tid*4;
  int v[4]; int loc = 0;
  #pragma unroll
  for (int i = 0; i < 4; i++){ int idx = base + i; v[i] = (idx < NN) ? g_deg[idx] : 0; loc += v[i]; }
  s[tid] = loc; __syncthreads();
  #pragma unroll
  for (int d = 1; d < 256; d <<= 1){
    int t = (tid >= d) ? s[tid-d] : 0; __syncthreads();
    s[tid] += t; __syncthreads();
  }
  int run = (tid == 0) ? 0 : s[tid-1];
  #pragma unroll
  for (int i = 0; i < 4; i++){ run += v[i]; int idx = base + i; if (idx < NN) g_off[idx] = run; }
  if (tid == 255) g_bsum[blockIdx.x] = s[255];
}

__global__ void k_scan23c(){
  int tid = threadIdx.x;
  int b = blockIdx.x;
  __shared__ int swarp[8];
  int v = (tid < b) ? g_bsum[tid] : 0;     // b <= 97 < 128
  #pragma unroll
  for (int o = 16; o; o >>= 1) v += __shfl_xor_sync(0xffffffffu, v, o);
  if ((tid & 31) == 0) swarp[tid >> 5] = v;
  __syncthreads();
  int pre = swarp[0] + swarp[1] + swarp[2] + swarp[3];
  int base = b*1024 + tid*4;
  #pragma unroll
  for (int i = 0; i < 4; i++){
    int idx = base + i;
    if (idx < NN){
      int off = g_off[idx] + pre;
      g_off[idx] = off;
      g_cursor[idx] = off - g_deg[idx];
    }
  }
}

__global__ void k_scatter(const int* __restrict__ ei){
  int e = blockIdx.x*blockDim.x + threadIdx.x;
  if (e < EE){
    int s = ei[e], d = ei[EE + e];
    int pos = atomicAdd(&g_cursor[d], 1);
    g_esrc[pos] = s;
  }
  if (e < NN) g_deg[e] = 0;   // re-zero for next replay (deg is dead by now)
}

// ---------------- attention scores (layer 1): thread-per-node ----------------
__global__ void __launch_bounds__(256) k_att1(const float* __restrict__ x,
                                              const float* __restrict__ W,
                                              const float* __restrict__ as_,
                                              const float* __restrict__ ad_){
  __shared__ float swa[2][16], swd[2][16];
  int tid = threadIdx.x;
  if (tid < 64){
    int h = (tid >> 4) & 1;
    int k = tid & 15;
    const float* att = (tid < 32) ? as_ : ad_;
    const float* wrow = W + k*128 + h*64;
    float acc = 0.f;
    #pragma unroll 16
    for (int c = 0; c < 64; c++) acc += wrow[c]*att[h*64 + c];
    if (tid < 32) swa[h][k] = acc; else swd[h][k] = acc;
  }
  __syncthreads();
  int n = blockIdx.x*blockDim.x + tid;
  if (n >= NN) return;
  float s0 = 0.f, s1 = 0.f, d0 = 0.f, d1 = 0.f;
  const float4* xr = (const float4*)(x + (size_t)n*16);
  #pragma unroll
  for (int q = 0; q < 4; q++){
    float4 v = xr[q];
    int k = 4*q;
    s0 += v.x*swa[0][k] + v.y*swa[0][k+1] + v.z*swa[0][k+2] + v.w*swa[0][k+3];
    s1 += v.x*swa[1][k] + v.y*swa[1][k+1] + v.z*swa[1][k+2] + v.w*swa[1][k+3];
    d0 += v.x*swd[0][k] + v.y*swd[0][k+1] + v.z*swd[0][k+2] + v.w*swd[0][k+3];
    d1 += v.x*swd[1][k] + v.y*swd[1][k+1] + v.z*swd[1][k+2] + v.w*swd[1][k+3];
  }
  ((float2*)g_as)[n] = make_float2(s0, s1);
  g_att[n] = make_float4(s0, s1, d0, d1);
}

// ---------------- attention scores (layers 2,3): thread-per-node, BN in regs -
// SRC: 1 = g_bufA, 2 = g_bufB
template<int SRC>
__global__ void __launch_bounds__(256) k_att2(const float* __restrict__ W,
                                              const float* __restrict__ as_,
                                              const float* __restrict__ ad_){
  const float* src = (SRC == 1) ? (const float*)g_bufA : (const float*)g_bufB;
  __shared__ float swa[2][64], swd[2][64];
  __shared__ float sbs[64], sbh[64];
  int tid = threadIdx.x;
  {
    int h = (tid >> 6) & 1;
    int k = tid & 63;
    const float* att = (tid < 128) ? as_ : ad_;
    const float* wrow = W + k*128 + h*64;
    float acc = 0.f;
    #pragma unroll 16
    for (int c = 0; c < 64; c++) acc += wrow[c]*att[h*64 + c];
    if (tid < 128) swa[h][k] = acc; else swd[h][k] = acc;
    if (tid < 64){ sbs[tid] = g_bnscale[tid]; sbh[tid] = g_bnshift[tid]; }
  }
  __syncthreads();
  int n = blockIdx.x*blockDim.x + tid;
  if (n >= NN) return;
  float s0 = 0.f, s1 = 0.f, d0 = 0.f, d1 = 0.f;
  const float4* xr = (const float4*)(src + (size_t)n*64);
  #pragma unroll
  for (int q = 0; q < 16; q++){
    float4 v = xr[q];
    int k = 4*q;
    v.x = fmaxf(fmaf(v.x, sbs[k],   sbh[k]),   0.f);
    v.y = fmaxf(fmaf(v.y, sbs[k+1], sbh[k+1]), 0.f);
    v.z = fmaxf(fmaf(v.z, sbs[k+2], sbh[k+2]), 0.f);
    v.w = fmaxf(fmaf(v.w, sbs[k+3], sbh[k+3]), 0.f);
    s0 += v.x*swa[0][k] + v.y*swa[0][k+1] + v.z*swa[0][k+2] + v.w*swa[0][k+3];
    s1 += v.x*swa[1][k] + v.y*swa[1][k+1] + v.z*swa[1][k+2] + v.w*swa[1][k+3];
    d0 += v.x*swd[0][k] + v.y*swd[0][k+1] + v.z*swd[0][k+2] + v.w*swd[0][k+3];
    d1 += v.x*swd[1][k] + v.y*swd[1][k+1] + v.z*swd[1][k+2] + v.w*swd[1][k+3];
  }
  ((float2*)g_as)[n] = make_float2(s0, s1);
  g_att[n] = make_float4(s0, s1, d0, d1);
}

// ---------------- FUSED layer: aggregate (16-lane group) -> smem y ->
//                  register-tiled GEMM (out 64) + BN stats + finalize ---------
// DS = input feature dim (16 or 64). SRCSEL: 0 = x param (no BN),
// 1 = g_bufA (BN fold), 2 = g_bufB (BN fold).
// Output: SRCSEL 0 -> g_bufA, 1 -> g_bufB, 2 -> g_bufA.
template<int DS, int SRCSEL>
__global__ void __launch_bounds__(256) k_layer(const float* __restrict__ xin,
                                               const float* __restrict__ W,
                                               const float* __restrict__ bias,
                                               const float* __restrict__ gam,
                                               const float* __restrict__ bet){
  constexpr int KK = 2*DS;       // GEMM in-dim
  constexpr int SP = KK + 4;     // padded row stride (floats), 16B-aligned rows
  __shared__ __align__(16) float sy [16*SP];
  __shared__ __align__(16) float swT[64*SP];
  __shared__ float srs0[256], srq0[256], srs1[256], srq1[256];
  __shared__ bool  lastb;

  const float* src = (SRCSEL == 0) ? xin
                   : (SRCSEL == 1) ? (const float*)g_bufA : (const float*)g_bufB;
  float* outp = (SRCSEL == 1) ? (float*)g_bufB : (float*)g_bufA;

  int tid = threadIdx.x;
  // transposed combined weight (0.5 head-average folded in)
  for (int idx = tid; idx < 64*KK; idx += 256){
    int j = idx / KK, k = idx % KK;
    float w = (k < DS) ? W[k*128 + j] : W[(k-DS)*128 + 64 + j];
    swT[j*SP + k] = 0.5f*w;
  }

  int grp = tid >> 4, lane = tid & 15;
  const unsigned gm = 0xFFFFu << (tid & 16);   // this 16-lane group's mask
  float4 sc4 = make_float4(0,0,0,0), sh4 = make_float4(0,0,0,0);
  if (DS == 64 && SRCSEL != 0){
    sc4 = ((const float4*)g_bnscale)[lane];
    sh4 = ((const float4*)g_bnshift)[lane];
  }
  int a = tid >> 5, bcol = tid & 31;
  int j0 = 2*bcol;
  float bj0 = bias[j0], bj1 = bias[j0+1];
  float bs0 = 0.f, bq0 = 0.f, bs1 = 0.f, bq1 = 0.f;
  __syncthreads();   // swT ready

  for (int base = blockIdx.x*16; base < NN; base += GL*16){
    // ================= aggregation phase (16 lanes per node) ================
    {
      int n = base + grp;          // NN % 16 == 0 -> always valid
      int start = n ? g_off[n-1] : 0;
      int end   = g_off[n];
      int len   = end - start;
      float4 attn = g_att[n];
      float ad0 = attn.z, ad1 = attn.w;
      float es0 = lrelu(attn.x + ad0);
      float es1 = lrelu(attn.y + ad1);

      if (DS == 16){
        float vs = src[(size_t)n*16 + lane];
        float y0, y1, den0, den1;
        if (len <= 16){
          int s = 0; float e0 = -1e30f, e1 = -1e30f;
          if (lane < len){
            s = g_esrc[start + lane];
            float2 aa = ((const float2*)g_as)[s];
            e0 = lrelu(aa.x + ad0); e1 = lrelu(aa.y + ad1);
          }
          float m0 = fmaxf(e0, es0), m1 = fmaxf(e1, es1);
          #pragma unroll
          for (int o = 8; o; o >>= 1){
            m0 = fmaxf(m0, __shfl_xor_sync(gm, m0, o, 16));
            m1 = fmaxf(m1, __shfl_xor_sync(gm, m1, o, 16));
          }
          float w0 = (lane < len) ? __expf(e0 - m0) : 0.f;
          float w1 = (lane < len) ? __expf(e1 - m1) : 0.f;
          float d0 = w0, d1 = w1;
          #pragma unroll
          for (int o = 8; o; o >>= 1){
            d0 += __shfl_xor_sync(gm, d0, o, 16);
            d1 += __shfl_xor_sync(gm, d1, o, 16);
          }
          float ws0 = __expf(es0 - m0), ws1 = __expf(es1 - m1);
          den0 = d0 + ws0 + 1e-16f; den1 = d1 + ws1 + 1e-16f;
          y0 = ws0*vs; y1 = ws1*vs;
          #pragma unroll 4
          for (int k = 0; k < len; k++){
            int   sk  = __shfl_sync(gm, s,  k, 16);
            float wk0 = __shfl_sync(gm, w0, k, 16);
            float wk1 = __shfl_sync(gm, w1, k, 16);
            float v = src[(size_t)sk*16 + lane];
            y0 += wk0*v; y1 += wk1*v;
          }
        } else {
          float m0 = es0, m1 = es1;
          for (int i = start + lane; i < end; i += 16){
            int s = g_esrc[i];
            float2 aa = ((const float2*)g_as)[s];
            m0 = fmaxf(m0, lrelu(aa.x + ad0));
            m1 = fmaxf(m1, lrelu(aa.y + ad1));
          }
          #pragma unroll
          for (int o = 8; o; o >>= 1){
            m0 = fmaxf(m0, __shfl_xor_sync(gm, m0, o, 16));
            m1 = fmaxf(m1, __shfl_xor_sync(gm, m1, o, 16));
          }
          float ws0 = __expf(es0 - m0), ws1 = __expf(es1 - m1);
          y0 = ws0*vs; y1 = ws1*vs;
          float d0 = 0.f, d1 = 0.f;
          for (int bb = start; bb < end; bb += 16){
            int cnt = min(16, end - bb);
            int s = 0; float w0 = 0.f, w1 = 0.f;
            if (lane < cnt){
              s = g_esrc[bb + lane];
              float2 aa = ((const float2*)g_as)[s];
              w0 = __expf(lrelu(aa.x + ad0) - m0);
              w1 = __expf(lrelu(aa.y + ad1) - m1);
            }
            d0 += w0; d1 += w1;
            for (int k = 0; k < cnt; k++){
              int   sk  = __shfl_sync(gm, s,  k, 16);
              float wk0 = __shfl_sync(gm, w0, k, 16);
              float wk1 = __shfl_sync(gm, w1, k, 16);
              float v = src[(size_t)sk*16 + lane];
              y0 += wk0*v; y1 += wk1*v;
            }
          }
          #pragma unroll
          for (int o = 8; o; o >>= 1){
            d0 += __shfl_xor_sync(gm, d0, o, 16);
            d1 += __shfl_xor_sync(gm, d1, o, 16);
          }
          den0 = d0 + ws0 + 1e-16f; den1 = d1 + ws1 + 1e-16f;
        }
        sy[grp*SP + lane]      = y0/den0;
        sy[grp*SP + 16 + lane] = y1/den1;
      } else {
        // DS == 64: lane holds 4 channels (float4); BN folded when SRCSEL != 0
        float4 vs = ((const float4*)(src + (size_t)n*64))[lane];
        if (SRCSEL != 0){
          vs.x = fmaxf(fmaf(vs.x, sc4.x, sh4.x), 0.f);
          vs.y = fmaxf(fmaf(vs.y, sc4.y, sh4.y), 0.f);
          vs.z = fmaxf(fmaf(vs.z, sc4.z, sh4.z), 0.f);
          vs.w = fmaxf(fmaf(vs.w, sc4.w, sh4.w), 0.f);
        }
        float4 y0, y1; float den0, den1;
        if (len <= 16){
          int s = 0; float e0 = -1e30f, e1 = -1e30f;
          if (lane < len){
            s = g_esrc[start + lane];
            float2 aa = ((const float2*)g_as)[s];
            e0 = lrelu(aa.x + ad0); e1 = lrelu(aa.y + ad1);
          }
          float m0 = fmaxf(e0, es0), m1 = fmaxf(e1, es1);
          #pragma unroll
          for (int o = 8; o; o >>= 1){
            m0 = fmaxf(m0, __shfl_xor_sync(gm, m0, o, 16));
            m1 = fmaxf(m1, __shfl_xor_sync(gm, m1, o, 16));
          }
          float w0 = (lane < len) ? __expf(e0 - m0) : 0.f;
          float w1 = (lane < len) ? __expf(e1 - m1) : 0.f;
          float d0 = w0, d1 = w1;
          #pragma unroll
          for (int o = 8; o; o >>= 1){
            d0 += __shfl_xor_sync(gm, d0, o, 16);
            d1 += __shfl_xor_sync(gm, d1, o, 16);
          }
          float ws0 = __expf(es0 - m0), ws1 = __expf(es1 - m1);
          den0 = d0 + ws0 + 1e-16f; den1 = d1 + ws1 + 1e-16f;
          y0.x = ws0*vs.x; y0.y = ws0*vs.y; y0.z = ws0*vs.z; y0.w = ws0*vs.w;
          y1.x = ws1*vs.x; y1.y = ws1*vs.y; y1.z = ws1*vs.z; y1.w = ws1*vs.w;
          #pragma unroll 4
          for (int k = 0; k < len; k++){
            int   sk  = __shfl_sync(gm, s,  k, 16);
            float wk0 = __shfl_sync(gm, w0, k, 16);
            float wk1 = __shfl_sync(gm, w1, k, 16);
            float4 v = ((const float4*)(src + (size_t)sk*64))[lane];
            if (SRCSEL != 0){
              v.x = fmaxf(fmaf(v.x, sc4.x, sh4.x), 0.f);
              v.y = fmaxf(fmaf(v.y, sc4.y, sh4.y), 0.f);
              v.z = fmaxf(fmaf(v.z, sc4.z, sh4.z), 0.f);
              v.w = fmaxf(fmaf(v.w, sc4.w, sh4.w), 0.f);
            }
            y0.x += wk0*v.x; y0.y += wk0*v.y; y0.z += wk0*v.z; y0.w += wk0*v.w;
            y1.x += wk1*v.x; y1.y += wk1*v.y; y1.z += wk1*v.z; y1.w += wk1*v.w;
          }
        } else {
          float m0 = es0, m1 = es1;
          for (int i = start + lane; i < end; i += 16){
            int s = g_esrc[i];
            float2 aa = ((const float2*)g_as)[s];
            m0 = fmaxf(m0, lrelu(aa.x + ad0));
            m1 = fmaxf(m1, lrelu(aa.y + ad1));
          }
          #pragma unroll
          for (int o = 8; o; o >>= 1){
            m0 = fmaxf(m0, __shfl_xor_sync(gm, m0, o, 16));
            m1 = fmaxf(m1, __shfl_xor_sync(gm, m1, o, 16));
          }
          float ws0 = __expf(es0 - m0), ws1 = __expf(es1 - m1);
          y0.x = ws0*vs.x; y0.y = ws0*vs.y; y0.z = ws0*vs.z; y0.w = ws0*vs.w;
          y1.x = ws1*vs.x; y1.y = ws1*vs.y; y1.z = ws1*vs.z; y1.w = ws1*vs.w;
          float d0 = 0.f, d1 = 0.f;
          for (int bb = start; bb < end; bb += 16){
            int cnt = min(16, end - bb);
            int s = 0; float w0 = 0.f, w1 = 0.f;
            if (lane < cnt){
              s = g_esrc[bb + lane];
              float2 aa = ((const float2*)g_as)[s];
              w0 = __expf(lrelu(aa.x + ad0) - m0);
              w1 = __expf(lrelu(aa.y + ad1) - m1);
            }
            d0 += w0; d1 += w1;
            for (int k = 0; k < cnt; k++){
              int   sk  = __shfl_sync(gm, s,  k, 16);
              float wk0 = __shfl_sync(gm, w0, k, 16);
              float wk1 = __shfl_sync(gm, w1, k, 16);
              float4 v = ((const float4*)(src + (size_t)sk*64))[lane];
              if (SRCSEL != 0){
                v.x = fmaxf(fmaf(v.x, sc4.x, sh4.x), 0.f);
                v.y = fmaxf(fmaf(v.y, sc4.y, sh4.y), 0.f);
                v.z = fmaxf(fmaf(v.z, sc4.z, sh4.z), 0.f);
                v.w = fmaxf(fmaf(v.w, sc4.w, sh4.w), 0.f);
              }
              y0.x += wk0*v.x; y0.y += wk0*v.y; y0.z += wk0*v.z; y0.w += wk0*v.w;
              y1.x += wk1*v.x; y1.y += wk1*v.y; y1.z += wk1*v.z; y1.w += wk1*v.w;
            }
          }
          #pragma unroll
          for (int o = 8; o; o >>= 1){
            d0 += __shfl_xor_sync(gm, d0, o, 16);
            d1 += __shfl_xor_sync(gm, d1, o, 16);
          }
          den0 = d0 + ws0 + 1e-16f; den1 = d1 + ws1 + 1e-16f;
        }
        float i0 = 1.f/den0, i1 = 1.f/den1;
        *(float4*)(sy + grp*SP + 4*lane) =
            make_float4(y0.x*i0, y0.y*i0, y0.z*i0, y0.w*i0);
        *(float4*)(sy + grp*SP + 64 + 4*lane) =
            make_float4(y1.x*i1, y1.y*i1, y1.z*i1, y1.w*i1);
      }
    }
    __syncthreads();
    // ================= GEMM phase: 2 nodes x 2 columns per thread ===========
    {
      int n0 = base + 2*a;
      const float* y0r = sy + (2*a)*SP;
      const float* y1r = y0r + SP;
      const float* w0r = swT + j0*SP;
      const float* w1r = w0r + SP;
      ull A00 = 0ull, A01 = 0ull, A10 = 0ull, A11 = 0ull;
      #pragma unroll 8
      for (int k4 = 0; k4 < KK/4; k4++){
        ulonglong2 ya = *(const ulonglong2*)(y0r + 4*k4);
        ulonglong2 yb = *(const ulonglong2*)(y1r + 4*k4);
        ulonglong2 wa = *(const ulonglong2*)(w0r + 4*k4);
        ulonglong2 wb = *(const ulonglong2*)(w1r + 4*k4);
        FMA2(A00, ya.x, wa.x, A00); FMA2(A00, ya.y, wa.y, A00);
        FMA2(A01, ya.x, wb.x, A01); FMA2(A01, ya.y, wb.y, A01);
        FMA2(A10, yb.x, wa.x, A10); FMA2(A10, yb.y, wa.y, A10);
        FMA2(A11, yb.x, wb.x, A11); FMA2(A11, yb.y, wb.y, A11);
      }
      float l, h;
      upk2(l, h, A00); float r00 = l + h + bj0;
      upk2(l, h, A01); float r01 = l + h + bj1;
      upk2(l, h, A10); float r10 = l + h + bj0;
      upk2(l, h, A11); float r11 = l + h + bj1;
      *(float2*)(outp + (size_t)n0*64 + j0)     = make_float2(r00, r01);
      *(float2*)(outp + (size_t)(n0+1)*64 + j0) = make_float2(r10, r11);
      bs0 += r00 + r10; bq0 += r00*r00 + r10*r10;
      bs1 += r01 + r11; bq1 += r01*r01 + r11*r11;
    }
    __syncthreads();
  }

  // ---------------- BN partials + last-block finalize ------------------------
  srs0[tid] = bs0; srq0[tid] = bq0; srs1[tid] = bs1; srq1[tid] = bq1;
  __syncthreads();
  if (tid < 64){
    int bc = tid >> 1;
    float ss = 0.f, qq = 0.f;
    if (tid & 1){
      #pragma unroll
      for (int aa = 0; aa < 8; aa++){ ss += srs1[aa*32 + bc]; qq += srq1[aa*32 + bc]; }
    } else {
      #pragma unroll
      for (int aa = 0; aa < 8; aa++){ ss += srs0[aa*32 + bc]; qq += srq0[aa*32 + bc]; }
    }
    g_part[blockIdx.x*128 + tid]      = ss;
    g_part[blockIdx.x*128 + 64 + tid] = qq;
  }
  __threadfence();
  if (tid == 0){
    lastb = (atomicAdd(&g_bncnt, 1) == (int)gridDim.x - 1);
    if (lastb) g_bncnt = 0;
  }
  __syncthreads();
  if (lastb && tid < 64){
    float ss = 0.f, qq = 0.f;
    #pragma unroll 8
    for (int bb = 0; bb < (int)gridDim.x; bb++){
      ss += __ldcg(&g_part[bb*128 + tid]);
      qq += __ldcg(&g_part[bb*128 + 64 + tid]);
    }
    const float inv = 1.f/(float)NN;
    float mean = ss*inv;
    float var  = qq*inv - mean*mean;
    float rstd = rsqrtf(var + 1e-5f);
    float scv  = rstd*gam[tid];
    g_bnscale[tid] = scv;
    g_bnshift[tid] = bet[tid] - mean*scv;
  }
}

// ---------------- MLP1 + heads fused (BN3 at load, hidden never stored) ------
__global__ void __launch_bounds__(256) k_mlp1h(const float* __restrict__ x,
                                               const float* __restrict__ W,
                                               const float* __restrict__ b,
                                               const float* __restrict__ W2,
                                               const float* __restrict__ b2,
                                               const float* __restrict__ pW,
                                               const float* __restrict__ pb,
                                               const float* __restrict__ vW,
                                               const float* __restrict__ vb,
                                               float* __restrict__ out){
  __shared__ float sq[64], sv[64], scst[2];
  __shared__ __align__(16) float sh[4][72];
  __shared__ float spart[8][2];
  int tid = threadIdx.x;
  int j = tid & 63, g = tid >> 6;
  if (tid < 128){
    int k = tid & 63;
    const float* hv = (tid < 64) ? pW : vW;
    const float* row = W2 + k*64;
    float acc = 0.f;
    #pragma unroll 16
    for (int c = 0; c < 64; c++) acc += row[c]*hv[c];
    if (tid < 64) sq[k] = acc; else sv[k] = acc;
  } else if (tid == 128){
    float a = 0.f, c = 0.f;
    #pragma unroll 16
    for (int jj = 0; jj < 64; jj++){ a += b2[jj]*pW[jj]; c += b2[jj]*vW[jj]; }
    scst[0] = a + pb[0];
    scst[1] = c + vb[0];
  }
  ull wp[34];
  #pragma unroll
  for (int k2 = 0; k2 < 34; k2++){
    float lo = W[(2*k2)*64 + j], hi = W[(2*k2+1)*64 + j];
    asm("mov.b64 %0, {%1, %2};" : "=l"(wp[k2]) : "f"(lo), "f"(hi));
  }
  float w68 = W[68*64 + j];
  float bj = b[j];
  float4 sc4, sh4;
  if (j < 16){
    sc4 = ((const float4*)g_bnscale)[j];
    sh4 = ((const float4*)g_bnshift)[j];
  }
  for (int n0 = blockIdx.x*4; n0 < NN; n0 += gridDim.x*4){
    int n = n0 + g;
    if (n < NN){
      if (j < 16){
        float4 v = ((const float4*)(g_bufA + (size_t)n*64))[j];
        v.x = fmaxf(fmaf(v.x, sc4.x, sh4.x), 0.f);
        v.y = fmaxf(fmaf(v.y, sc4.y, sh4.y), 0.f);
        v.z = fmaxf(fmaf(v.z, sc4.z, sh4.z), 0.f);
        v.w = fmaxf(fmaf(v.w, sc4.w, sh4.w), 0.f);
        ((float4*)sh[g])[j] = v;
      }
      if (j >= 16 && j < 21) sh[g][48 + j] = x[(size_t)n*16 + (j - 7)];  // ctx = x[:,9:14]
    }
    __syncthreads();
    float lp = 0.f, vp = 0.f;
    {
      ull a0 = 0ull, a1 = 0ull;
      const ull* yp = (const ull*)sh[g];
      #pragma unroll
      for (int k2 = 0; k2 < 34; k2 += 2){
        FMA2(a0, yp[k2],   wp[k2],   a0);
        FMA2(a1, yp[k2+1], wp[k2+1], a1);
      }
      float l0,h0,l1,h1; upk2(l0,h0,a0); upk2(l1,h1,a1);
      float t = fmaxf((l0+h0)+(l1+h1) + sh[g][68]*w68 + bj, 0.f);
      if (n < NN){ lp = t*sq[j]; vp = t*sv[j]; }
    }
    #pragma unroll
    for (int o = 16; o; o >>= 1){
      lp += __shfl_xor_sync(0xffffffffu, lp, o);
      vp += __shfl_xor_sync(0xffffffffu, vp, o);
    }
    int w = tid >> 5;
    if ((tid & 31) == 0){ spart[w][0] = lp; spart[w][1] = vp; }
    __syncthreads();
    if (tid < 4){
      int nn = n0 + tid;
      if (nn < NN){
        out[nn]      = spart[2*tid][0] + spart[2*tid+1][0] + scst[0];
        out[NN + nn] = spart[2*tid][1] + spart[2*tid+1][1] + scst[1];
      }
    }
    __syncthreads();
  }
}

// ---------------- launch -----------------------------------------------------
extern "C" void kernel_launch(void* const* d_in, const int* in_sizes, int n_in,
                              void* d_out, int out_size){
  const float* x   = (const float*)d_in[0];
  const int*   ei  = (const int*)  d_in[1];
  const float* W1  = (const float*)d_in[2];
  const float* as1 = (const float*)d_in[3];
  const float* ad1 = (const float*)d_in[4];
  const float* b1  = (const float*)d_in[5];
  const float* g1  = (const float*)d_in[6];
  const float* be1 = (const float*)d_in[7];
  const float* W2  = (const float*)d_in[8];
  const float* as2 = (const float*)d_in[9];
  const float* ad2 = (const float*)d_in[10];
  const float* b2  = (const float*)d_in[11];
  const float* g2  = (const float*)d_in[12];
  const float* be2 = (const float*)d_in[13];
  const float* W3  = (const float*)d_in[14];
  const float* as3 = (const float*)d_in[15];
  const float* ad3 = (const float*)d_in[16];
  const float* b3  = (const float*)d_in[17];
  const float* g3  = (const float*)d_in[18];
  const float* be3 = (const float*)d_in[19];
  const float* mW1 = (const float*)d_in[20];
  const float* mb1 = (const float*)d_in[21];
  const float* mW2 = (const float*)d_in[22];
  const float* mb2 = (const float*)d_in[23];
  const float* pW  = (const float*)d_in[24];
  const float* pb  = (const float*)d_in[25];
  const float* vW  = (const float*)d_in[26];
  const float* vb  = (const float*)d_in[27];
  float* out = (float*)d_out;

  const int TB = 256;
  const int gE   = (EE + TB - 1)/TB;
  const int gN   = (NN + TB - 1)/TB;
  const int gMlp = 1184;

  // CSR + att1 (k_att1 at launch index 3 so ncu profiles it)
  k_count<<<gE, TB>>>(ei);
  k_scan1<<<NB1, TB>>>();
  k_scan23c<<<NB1, TB>>>();
  k_att1<<<gN, TB>>>(x, W1, as1, ad1);
  k_scatter<<<gE, TB>>>(ei);

  // layer 1 (D=16, raw x) -> g_bufA, bn1
  k_layer<16,0><<<GL, TB>>>(x, W1, b1, g1, be1);

  // layer 2: att from g_bufA, aggregate g_bufA -> g_bufB, bn2
  k_att2<1><<<gN, TB>>>(W2, as2, ad2);
  k_layer<64,1><<<GL, TB>>>(nullptr, W2, b2, g2, be2);

  // layer 3: att from g_bufB, aggregate g_bufB -> g_bufA, bn3
  k_att2<2><<<gN, TB>>>(W3, as3, ad3);
  k_layer<64,2><<<GL, TB>>>(nullptr, W3, b3, g3, be3);

  // MLP + heads (fused), reads g_bufA + bn3
  k_mlp1h<<<gMlp, TB>>>(x, mW1, mb1, mW2, mb2, pW, pb, vW, vb, out);
}

// round 11
// speedup vs baseline: 1.0785x; 1.0785x over previous
#include <cuda_runtime.h>
#include <math.h>

#define NN 100000
#define EE 1000000
#define NB1 98     // ceil(NN/1024)
#define GOUT 592   // grid for k_out

typedef unsigned long long ull;

// ---------------- scratch (static device globals; no allocation) -------------
__device__ float  g_z[(size_t)NN*128];     // aggregated per-head features
__device__ float  g_buf64[(size_t)NN*64];  // layer output (pre-BN)
__device__ float  g_as[NN*2];              // per-node src scores
__device__ float4 g_att[NN];               // (as0, as1, ad0, ad1) per node
__device__ int    g_deg[NN];               // zero-init; re-zeroed by k_scatter
__device__ int    g_off[NN];
__device__ int    g_cursor[NN];
__device__ int    g_esrc[EE];
__device__ int    g_bsum[128];
__device__ float  g_part[GOUT*128];        // BN partials per k_out block
__device__ float  g_bnscale[64];
__device__ float  g_bnshift[64];
__device__ int    g_bncnt;
__device__ int    g_scancnt;
__device__ int    g_scandone;

__device__ __forceinline__ float lrelu(float v){ return v > 0.f ? v : 0.2f*v; }

__device__ __forceinline__ ull pk2(float lo, float hi){
  ull u; asm("mov.b64 %0, {%1, %2};" : "=l"(u) : "f"(lo), "f"(hi)); return u;
}
__device__ __forceinline__ void upk2(float& lo, float& hi, ull u){
  asm("mov.b64 {%0, %1}, %2;" : "=f"(lo), "=f"(hi) : "l"(u));
}
#define FMA2(d, a, b, c) \
  asm("fma.rn.f32x2 %0, %1, %2, %3;" : "=l"(d) : "l"(a), "l"(b), "l"(c))

// ---------------- fused: degree count + layer-1 attention scores -------------
__global__ void __launch_bounds__(256) k_attcount(const int* __restrict__ ei,
                                                  const float* __restrict__ x,
                                                  const float* __restrict__ W,
                                                  const float* __restrict__ as_,
                                                  const float* __restrict__ ad_){
  __shared__ float swa[2][16], swd[2][16];
  int tid = threadIdx.x;
  int e = blockIdx.x*blockDim.x + tid;
  bool doatt = (e < NN);
  if (doatt && tid < 64){
    int h = (tid >> 4) & 1;
    int k = tid & 15;
    const float* att = (tid < 32) ? as_ : ad_;
    const float* wrow = W + k*128 + h*64;
    float acc = 0.f;
    #pragma unroll 16
    for (int c = 0; c < 64; c++) acc += wrow[c]*att[h*64 + c];
    if (tid < 32) swa[h][k] = acc; else swd[h][k] = acc;
  }
  if (e < EE) atomicAdd(&g_deg[ei[EE + e]], 1);
  if (!doatt) return;
  __syncthreads();
  int n = e;
  float s0 = 0.f, s1 = 0.f, d0 = 0.f, d1 = 0.f;
  const float4* xr = (const float4*)(x + (size_t)n*16);
  #pragma unroll
  for (int q = 0; q < 4; q++){
    float4 v = xr[q];
    int k = 4*q;
    s0 += v.x*swa[0][k] + v.y*swa[0][k+1] + v.z*swa[0][k+2] + v.w*swa[0][k+3];
    s1 += v.x*swa[1][k] + v.y*swa[1][k+1] + v.z*swa[1][k+2] + v.w*swa[1][k+3];
    d0 += v.x*swd[0][k] + v.y*swd[0][k+1] + v.z*swd[0][k+2] + v.w*swd[0][k+3];
    d1 += v.x*swd[1][k] + v.y*swd[1][k+1] + v.z*swd[1][k+2] + v.w*swd[1][k+3];
  }
  ((float2*)g_as)[n] = make_float2(s0, s1);
  g_att[n] = make_float4(s0, s1, d0, d1);
}

// ---------------- fused scan: local scan + spin-wait grid sync + prefix ------
// 98 blocks, all resident (<=148 SMs) -> spin is deadlock-free.
__global__ void __launch_bounds__(256) k_scanall(){
  __shared__ int s[256];
  __shared__ int swarp[8];
  int tid = threadIdx.x;
  int b = blockIdx.x;
  int base = b*1024 + tid*4;
  int v[4]; int loc = 0;
  #pragma unroll
  for (int i = 0; i < 4; i++){ int idx = base + i; v[i] = (idx < NN) ? g_deg[idx] : 0; loc += v[i]; }
  s[tid] = loc; __syncthreads();
  #pragma unroll
  for (int d = 1; d < 256; d <<= 1){
    int t = (tid >= d) ? s[tid-d] : 0; __syncthreads();
    s[tid] += t; __syncthreads();
  }
  int run = (tid == 0) ? 0 : s[tid-1];
  #pragma unroll
  for (int i = 0; i < 4; i++){ run += v[i]; int idx = base + i; if (idx < NN) g_off[idx] = run; }
  if (tid == 255){
    g_bsum[b] = s[255];
    __threadfence();
    atomicAdd(&g_scancnt, 1);
  }
  // grid barrier: spin until all 98 blocks published their totals
  if (tid == 0){
    while (atomicAdd(&g_scancnt, 0) < NB1) { }
  }
  __syncthreads();
  // prefix of block sums before b
  {
    int vv = (tid < b) ? g_bsum[tid] : 0;     // b <= 97 < 128 -> tid<128 covers
    #pragma unroll
    for (int o = 16; o; o >>= 1) vv += __shfl_xor_sync(0xffffffffu, vv, o);
    if ((tid & 31) == 0) swarp[tid >> 5] = vv;
  }
  __syncthreads();
  int pre = swarp[0] + swarp[1] + swarp[2] + swarp[3];
  #pragma unroll
  for (int i = 0; i < 4; i++){
    int idx = base + i;
    if (idx < NN){
      int off = g_off[idx] + pre;
      g_off[idx] = off;
      g_cursor[idx] = off - g_deg[idx];
    }
  }
  __syncthreads();
  if (tid == 0){
    int d = atomicAdd(&g_scandone, 1);
    if (d == NB1-1){ g_scancnt = 0; g_scandone = 0; }   // replay-safe reset
  }
}

__global__ void k_scatter(const int* __restrict__ ei){
  int e = blockIdx.x*blockDim.x + threadIdx.x;
  if (e < EE){
    int s = ei[e], d = ei[EE + e];
    int pos = atomicAdd(&g_cursor[d], 1);
    g_esrc[pos] = s;
  }
  if (e < NN) g_deg[e] = 0;   // re-zero for next replay (deg is dead by now)
}

// ---------------- attention scores (layers 2,3): thread-per-node, BN in regs -
__global__ void __launch_bounds__(256) k_att2(const float* __restrict__ W,
                                              const float* __restrict__ as_,
                                              const float* __restrict__ ad_){
  __shared__ float swa[2][64], swd[2][64];
  __shared__ float sbs[64], sbh[64];
  int tid = threadIdx.x;
  {
    int h = (tid >> 6) & 1;
    int k = tid & 63;
    const float* att = (tid < 128) ? as_ : ad_;
    const float* wrow = W + k*128 + h*64;
    float acc = 0.f;
    #pragma unroll 16
    for (int c = 0; c < 64; c++) acc += wrow[c]*att[h*64 + c];
    if (tid < 128) swa[h][k] = acc; else swd[h][k] = acc;
    if (tid < 64){ sbs[tid] = g_bnscale[tid]; sbh[tid] = g_bnshift[tid]; }
  }
  __syncthreads();
  int n = blockIdx.x*blockDim.x + tid;
  if (n >= NN) return;
  float s0 = 0.f, s1 = 0.f, d0 = 0.f, d1 = 0.f;
  const float4* xr = (const float4*)(g_buf64 + (size_t)n*64);
  #pragma unroll
  for (int q = 0; q < 16; q++){
    float4 v = xr[q];
    int k = 4*q;
    v.x = fmaxf(fmaf(v.x, sbs[k],   sbh[k]),   0.f);
    v.y = fmaxf(fmaf(v.y, sbs[k+1], sbh[k+1]), 0.f);
    v.z = fmaxf(fmaf(v.z, sbs[k+2], sbh[k+2]), 0.f);
    v.w = fmaxf(fmaf(v.w, sbs[k+3], sbh[k+3]), 0.f);
    s0 += v.x*swa[0][k] + v.y*swa[0][k+1] + v.z*swa[0][k+2] + v.w*swa[0][k+3];
    s1 += v.x*swa[1][k] + v.y*swa[1][k+1] + v.z*swa[1][k+2] + v.w*swa[1][k+3];
    d0 += v.x*swd[0][k] + v.y*swd[0][k+1] + v.z*swd[0][k+2] + v.w*swd[0][k+3];
    d1 += v.x*swd[1][k] + v.y*swd[1][k+1] + v.z*swd[1][k+2] + v.w*swd[1][k+3];
  }
  ((float2*)g_as)[n] = make_float2(s0, s1);
  g_att[n] = make_float4(s0, s1, d0, d1);
}

// ---------------- GAT aggregation: 16-lane group per node --------------------
// Layer 1 (D=16): lane holds 1 channel; raw x input, no BN.
__global__ void __launch_bounds__(256) k_agg16(const float* __restrict__ x){
  int t = blockIdx.x*blockDim.x + threadIdx.x;
  int n = t >> 4, lane = t & 15;
  if (n >= NN) return;
  const unsigned gm = 0xFFFFu << (threadIdx.x & 16);   // this group's mask
  int start = n ? g_off[n-1] : 0;
  int end   = g_off[n];
  int len   = end - start;
  float4 attn = g_att[n];
  float ad0 = attn.z, ad1 = attn.w;
  float es0 = lrelu(attn.x + ad0);
  float es1 = lrelu(attn.y + ad1);
  float vs = x[(size_t)n*16 + lane];
  float y0, y1, den0, den1;

  if (len <= 16){
    int s = 0; float e0 = -1e30f, e1 = -1e30f;
    if (lane < len){
      s = g_esrc[start + lane];
      float2 a = ((const float2*)g_as)[s];
      e0 = lrelu(a.x + ad0);
      e1 = lrelu(a.y + ad1);
    }
    float m0 = fmaxf(e0, es0), m1 = fmaxf(e1, es1);
    #pragma unroll
    for (int o = 8; o; o >>= 1){
      m0 = fmaxf(m0, __shfl_xor_sync(gm, m0, o, 16));
      m1 = fmaxf(m1, __shfl_xor_sync(gm, m1, o, 16));
    }
    float w0 = (lane < len) ? __expf(e0 - m0) : 0.f;
    float w1 = (lane < len) ? __expf(e1 - m1) : 0.f;
    float d0 = w0, d1 = w1;
    #pragma unroll
    for (int o = 8; o; o >>= 1){
      d0 += __shfl_xor_sync(gm, d0, o, 16);
      d1 += __shfl_xor_sync(gm, d1, o, 16);
    }
    float ws0 = __expf(es0 - m0), ws1 = __expf(es1 - m1);
    den0 = d0 + ws0 + 1e-16f;
    den1 = d1 + ws1 + 1e-16f;
    y0 = ws0*vs; y1 = ws1*vs;
    #pragma unroll 4
    for (int k = 0; k < len; k++){
      int   sk  = __shfl_sync(gm, s,  k, 16);
      float wk0 = __shfl_sync(gm, w0, k, 16);
      float wk1 = __shfl_sync(gm, w1, k, 16);
      float v = x[(size_t)sk*16 + lane];
      y0 += wk0*v; y1 += wk1*v;
    }
  } else {
    float m0 = es0, m1 = es1;
    for (int i = start + lane; i < end; i += 16){
      int s = g_esrc[i];
      float2 a = ((const float2*)g_as)[s];
      m0 = fmaxf(m0, lrelu(a.x + ad0));
      m1 = fmaxf(m1, lrelu(a.y + ad1));
    }
    #pragma unroll
    for (int o = 8; o; o >>= 1){
      m0 = fmaxf(m0, __shfl_xor_sync(gm, m0, o, 16));
      m1 = fmaxf(m1, __shfl_xor_sync(gm, m1, o, 16));
    }
    float ws0 = __expf(es0 - m0), ws1 = __expf(es1 - m1);
    y0 = ws0*vs; y1 = ws1*vs;
    float d0 = 0.f, d1 = 0.f;
    for (int base = start; base < end; base += 16){
      int cnt = min(16, end - base);
      int s = 0; float w0 = 0.f, w1 = 0.f;
      if (lane < cnt){
        s = g_esrc[base + lane];
        float2 a = ((const float2*)g_as)[s];
        w0 = __expf(lrelu(a.x + ad0) - m0);
        w1 = __expf(lrelu(a.y + ad1) - m1);
      }
      d0 += w0; d1 += w1;
      for (int k = 0; k < cnt; k++){
        int   sk  = __shfl_sync(gm, s,  k, 16);
        float wk0 = __shfl_sync(gm, w0, k, 16);
        float wk1 = __shfl_sync(gm, w1, k, 16);
        float v = x[(size_t)sk*16 + lane];
        y0 += wk0*v; y1 += wk1*v;
      }
    }
    #pragma unroll
    for (int o = 8; o; o >>= 1){
      d0 += __shfl_xor_sync(gm, d0, o, 16);
      d1 += __shfl_xor_sync(gm, d1, o, 16);
    }
    den0 = d0 + ws0 + 1e-16f;
    den1 = d1 + ws1 + 1e-16f;
  }

  float* zr = g_z + (size_t)n*32;
  zr[lane]      = y0/den0;
  zr[16 + lane] = y1/den1;
}

// Layers 2,3 (D=64): lane holds 4 channels (float4); BN+relu folded into gather.
__global__ void __launch_bounds__(256) k_agg64(){
  int t = blockIdx.x*blockDim.x + threadIdx.x;
  int n = t >> 4, lane = t & 15;
  if (n >= NN) return;
  const unsigned gm = 0xFFFFu << (threadIdx.x & 16);   // this group's mask
  float4 sc4 = ((const float4*)g_bnscale)[lane];
  float4 sh4 = ((const float4*)g_bnshift)[lane];
  int start = n ? g_off[n-1] : 0;
  int end   = g_off[n];
  int len   = end - start;
  float4 attn = g_att[n];
  float ad0 = attn.z, ad1 = attn.w;
  float es0 = lrelu(attn.x + ad0);
  float es1 = lrelu(attn.y + ad1);
  float4 vs = ((const float4*)(g_buf64 + (size_t)n*64))[lane];
  vs.x = fmaxf(fmaf(vs.x, sc4.x, sh4.x), 0.f);
  vs.y = fmaxf(fmaf(vs.y, sc4.y, sh4.y), 0.f);
  vs.z = fmaxf(fmaf(vs.z, sc4.z, sh4.z), 0.f);
  vs.w = fmaxf(fmaf(vs.w, sc4.w, sh4.w), 0.f);
  float4 y0, y1;
  float den0, den1;

  if (len <= 16){
    int s = 0; float e0 = -1e30f, e1 = -1e30f;
    if (lane < len){
      s = g_esrc[start + lane];
      float2 a = ((const float2*)g_as)[s];
      e0 = lrelu(a.x + ad0);
      e1 = lrelu(a.y + ad1);
    }
    float m0 = fmaxf(e0, es0), m1 = fmaxf(e1, es1);
    #pragma unroll
    for (int o = 8; o; o >>= 1){
      m0 = fmaxf(m0, __shfl_xor_sync(gm, m0, o, 16));
      m1 = fmaxf(m1, __shfl_xor_sync(gm, m1, o, 16));
    }
    float w0 = (lane < len) ? __expf(e0 - m0) : 0.f;
    float w1 = (lane < len) ? __expf(e1 - m1) : 0.f;
    float d0 = w0, d1 = w1;
    #pragma unroll
    for (int o = 8; o; o >>= 1){
      d0 += __shfl_xor_sync(gm, d0, o, 16);
      d1 += __shfl_xor_sync(gm, d1, o, 16);
    }
    float ws0 = __expf(es0 - m0), ws1 = __expf(es1 - m1);
    den0 = d0 + ws0 + 1e-16f;
    den1 = d1 + ws1 + 1e-16f;
    y0.x = ws0*vs.x; y0.y = ws0*vs.y; y0.z = ws0*vs.z; y0.w = ws0*vs.w;
    y1.x = ws1*vs.x; y1.y = ws1*vs.y; y1.z = ws1*vs.z; y1.w = ws1*vs.w;
    #pragma unroll 4
    for (int k = 0; k < len; k++){
      int   sk  = __shfl_sync(gm, s,  k, 16);
      float wk0 = __shfl_sync(gm, w0, k, 16);
      float wk1 = __shfl_sync(gm, w1, k, 16);
      float4 v = ((const float4*)(g_buf64 + (size_t)sk*64))[lane];
      v.x = fmaxf(fmaf(v.x, sc4.x, sh4.x), 0.f);
      v.y = fmaxf(fmaf(v.y, sc4.y, sh4.y), 0.f);
      v.z = fmaxf(fmaf(v.z, sc4.z, sh4.z), 0.f);
      v.w = fmaxf(fmaf(v.w, sc4.w, sh4.w), 0.f);
      y0.x += wk0*v.x; y0.y += wk0*v.y; y0.z += wk0*v.z; y0.w += wk0*v.w;
      y1.x += wk1*v.x; y1.y += wk1*v.y; y1.z += wk1*v.z; y1.w += wk1*v.w;
    }
  } else {
    float m0 = es0, m1 = es1;
    for (int i = start + lane; i < end; i += 16){
      int s = g_esrc[i];
      float2 a = ((const float2*)g_as)[s];
      m0 = fmaxf(m0, lrelu(a.x + ad0));
      m1 = fmaxf(m1, lrelu(a.y + ad1));
    }
    #pragma unroll
    for (int o = 8; o; o >>= 1){
      m0 = fmaxf(m0, __shfl_xor_sync(gm, m0, o, 16));
      m1 = fmaxf(m1, __shfl_xor_sync(gm, m1, o, 16));
    }
    float ws0 = __expf(es0 - m0), ws1 = __expf(es1 - m1);
    y0.x = ws0*vs.x; y0.y = ws0*vs.y; y0.z = ws0*vs.z; y0.w = ws0*vs.w;
    y1.x = ws1*vs.x; y1.y = ws1*vs.y; y1.z = ws1*vs.z; y1.w = ws1*vs.w;
    float d0 = 0.f, d1 = 0.f;
    for (int base = start; base < end; base += 16){
      int cnt = min(16, end - base);
      int s = 0; float w0 = 0.f, w1 = 0.f;
      if (lane < cnt){
        s = g_esrc[base + lane];
        float2 a = ((const float2*)g_as)[s];
        w0 = __expf(lrelu(a.x + ad0) - m0);
        w1 = __expf(lrelu(a.y + ad1) - m1);
      }
      d0 += w0; d1 += w1;
      for (int k = 0; k < cnt; k++){
        int   sk  = __shfl_sync(gm, s,  k, 16);
        float wk0 = __shfl_sync(gm, w0, k, 16);
        float wk1 = __shfl_sync(gm, w1, k, 16);
        float4 v = ((const float4*)(g_buf64 + (size_t)sk*64))[lane];
        v.x = fmaxf(fmaf(v.x, sc4.x, sh4.x), 0.f);
        v.y = fmaxf(fmaf(v.y, sc4.y, sh4.y), 0.f);
        v.z = fmaxf(fmaf(v.z, sc4.z, sh4.z), 0.f);
        v.w = fmaxf(fmaf(v.w, sc4.w, sh4.w), 0.f);
        y0.x += wk0*v.x; y0.y += wk0*v.y; y0.z += wk0*v.z; y0.w += wk0*v.w;
        y1.x += wk1*v.x; y1.y += wk1*v.y; y1.z += wk1*v.z; y1.w += wk1*v.w;
      }
    }
    #pragma unroll
    for (int o = 8; o; o >>= 1){
      d0 += __shfl_xor_sync(gm, d0, o, 16);
      d1 += __shfl_xor_sync(gm, d1, o, 16);
    }
    den0 = d0 + ws0 + 1e-16f;
    den1 = d1 + ws1 + 1e-16f;
  }

  float i0 = 1.f/den0, i1 = 1.f/den1;
  float4* zr = (float4*)(g_z + (size_t)n*128);
  zr[lane]      = make_float4(y0.x*i0, y0.y*i0, y0.z*i0, y0.w*i0);
  zr[16 + lane] = make_float4(y1.x*i1, y1.y*i1, y1.z*i1, y1.w*i1);
}

// ---------------- output transform: 8 nodes per barrier pair -----------------
template<int D>
__global__ void __launch_bounds__(256) k_out(const float* __restrict__ W,
                                             const float* __restrict__ b,
                                             const float* __restrict__ gam,
                                             const float* __restrict__ bet){
  int tid = threadIdx.x;
  int g   = tid >> 7;
  int idx = tid & 127;
  int j   = idx >> 1;
  int hb  = idx & 1;
  ull wp[D/2];
  #pragma unroll
  for (int k2 = 0; k2 < D/2; k2++)
    wp[k2] = pk2(0.5f*W[(2*k2)*128 + hb*64 + j], 0.5f*W[(2*k2+1)*128 + hb*64 + j]);
  float bj = b[j];
  __shared__ __align__(16) float sy[8][2*D];
  __shared__ float sacc[256];
  float bs = 0.f, bq = 0.f;
  const int F4 = D/2;                  // float4 per row
  for (int n0 = blockIdx.x*8; n0 < NN; n0 += GOUT*8){
    if (tid < 4*D){
      int row = tid / F4;
      int col = tid % F4;
      int n = n0 + row;
      if (n < NN)
        ((float4*)sy[row])[col] = ((const float4*)(g_z + (size_t)n*(2*D)))[col];
    }
    __syncthreads();
    #pragma unroll
    for (int i = 0; i < 4; i++){
      int n = n0 + g*4 + i;
      const ull* yp = (const ull*)(sy[g*4+i] + hb*D);
      ull a0 = 0ull, a1 = 0ull;
      #pragma unroll
      for (int k2 = 0; k2 < D/2; k2 += 2){
        FMA2(a0, yp[k2],   wp[k2],   a0);
        FMA2(a1, yp[k2+1], wp[k2+1], a1);
      }
      float l0,h0,l1,h1; upk2(l0,h0,a0); upk2(l1,h1,a1);
      float partial = (l0+h0)+(l1+h1);
      float comb = partial + __shfl_xor_sync(0xffffffffu, partial, 1);
      if (hb == 0 && n < NN){
        float r = comb + bj;
        g_buf64[(size_t)n*64 + j] = r;
        bs += r; bq += r*r;
      }
    }
    __syncthreads();
  }
  sacc[tid] = bs;
  __syncthreads();
  float ts = 0.f;
  if (tid < 64) ts = sacc[2*tid] + sacc[128 + 2*tid];
  __syncthreads();
  sacc[tid] = bq;
  __syncthreads();
  if (tid < 64){
    g_part[blockIdx.x*128 + tid]      = ts;
    g_part[blockIdx.x*128 + 64 + tid] = sacc[2*tid] + sacc[128 + 2*tid];
  }
  __threadfence();
  __shared__ bool lastb;
  if (tid == 0){
    lastb = (atomicAdd(&g_bncnt, 1) == GOUT-1);
    if (lastb) g_bncnt = 0;
  }
  __syncthreads();
  if (lastb && tid < 64){
    float ss = 0.f, qq = 0.f;
    #pragma unroll 8
    for (int bb = 0; bb < GOUT; bb++){
      ss += __ldcg(&g_part[bb*128 + tid]);
      qq += __ldcg(&g_part[bb*128 + 64 + tid]);
    }
    const float inv = 1.f/(float)NN;
    float mean = ss*inv;
    float var  = qq*inv - mean*mean;
    float rstd = rsqrtf(var + 1e-5f);
    float scv = rstd*gam[tid];
    g_bnscale[tid] = scv;
    g_bnshift[tid] = bet[tid] - mean*scv;
  }
}

// ---------------- MLP1 + heads fused (BN3 at load, hidden never stored) ------
__global__ void __launch_bounds__(256) k_mlp1h(const float* __restrict__ x,
                                               const float* __restrict__ W,
                                               const float* __restrict__ b,
                                               const float* __restrict__ W2,
                                               const float* __restrict__ b2,
                                               const float* __restrict__ pW,
                                               const float* __restrict__ pb,
                                               const float* __restrict__ vW,
                                               const float* __restrict__ vb,
                                               float* __restrict__ out){
  __shared__ float sq[64], sv[64], scst[2];
  __shared__ __align__(16) float sh[4][72];
  __shared__ float spart[8][2];
  int tid = threadIdx.x;
  int j = tid & 63, g = tid >> 6;
  if (tid < 128){
    int k = tid & 63;
    const float* hv = (tid < 64) ? pW : vW;
    const float* row = W2 + k*64;
    float acc = 0.f;
    #pragma unroll 16
    for (int c = 0; c < 64; c++) acc += row[c]*hv[c];
    if (tid < 64) sq[k] = acc; else sv[k] = acc;
  } else if (tid == 128){
    float a = 0.f, c = 0.f;
    #pragma unroll 16
    for (int jj = 0; jj < 64; jj++){ a += b2[jj]*pW[jj]; c += b2[jj]*vW[jj]; }
    scst[0] = a + pb[0];
    scst[1] = c + vb[0];
  }
  ull wp[34];
  #pragma unroll
  for (int k2 = 0; k2 < 34; k2++)
    wp[k2] = pk2(W[(2*k2)*64 + j], W[(2*k2+1)*64 + j]);
  float w68 = W[68*64 + j];
  float bj = b[j];
  float4 sc4, sh4;
  if (j < 16){
    sc4 = ((const float4*)g_bnscale)[j];
    sh4 = ((const float4*)g_bnshift)[j];
  }
  for (int n0 = blockIdx.x*4; n0 < NN; n0 += gridDim.x*4){
    int n = n0 + g;
    if (n < NN){
      if (j < 16){
        float4 v = ((const float4*)(g_buf64 + (size_t)n*64))[j];
        v.x = fmaxf(fmaf(v.x, sc4.x, sh4.x), 0.f);
        v.y = fmaxf(fmaf(v.y, sc4.y, sh4.y), 0.f);
        v.z = fmaxf(fmaf(v.z, sc4.z, sh4.z), 0.f);
        v.w = fmaxf(fmaf(v.w, sc4.w, sh4.w), 0.f);
        ((float4*)sh[g])[j] = v;
      }
      if (j >= 16 && j < 21) sh[g][48 + j] = x[(size_t)n*16 + (j - 7)];  // ctx = x[:,9:14]
    }
    __syncthreads();
    float lp = 0.f, vp = 0.f;
    {
      ull a0 = 0ull, a1 = 0ull;
      const ull* yp = (const ull*)sh[g];
      #pragma unroll
      for (int k2 = 0; k2 < 34; k2 += 2){
        FMA2(a0, yp[k2],   wp[k2],   a0);
        FMA2(a1, yp[k2+1], wp[k2+1], a1);
      }
      float l0,h0,l1,h1; upk2(l0,h0,a0); upk2(l1,h1,a1);
      float t = fmaxf((l0+h0)+(l1+h1) + sh[g][68]*w68 + bj, 0.f);
      if (n < NN){ lp = t*sq[j]; vp = t*sv[j]; }
    }
    #pragma unroll
    for (int o = 16; o; o >>= 1){
      lp += __shfl_xor_sync(0xffffffffu, lp, o);
      vp += __shfl_xor_sync(0xffffffffu, vp, o);
    }
    int w = tid >> 5;
    if ((tid & 31) == 0){ spart[w][0] = lp; spart[w][1] = vp; }
    __syncthreads();
    if (tid < 4){
      int nn = n0 + tid;
      if (nn < NN){
        out[nn]      = spart[2*tid][0] + spart[2*tid+1][0] + scst[0];
        out[NN + nn] = spart[2*tid][1] + spart[2*tid+1][1] + scst[1];
      }
    }
    __syncthreads();
  }
}

// ---------------- launch -----------------------------------------------------
extern "C" void kernel_launch(void* const* d_in, const int* in_sizes, int n_in,
                              void* d_out, int out_size){
  const float* x   = (const float*)d_in[0];
  const int*   ei  = (const int*)  d_in[1];
  const float* W1  = (const float*)d_in[2];
  const float* as1 = (const float*)d_in[3];
  const float* ad1 = (const float*)d_in[4];
  const float* b1  = (const float*)d_in[5];
  const float* g1  = (const float*)d_in[6];
  const float* be1 = (const float*)d_in[7];
  const float* W2  = (const float*)d_in[8];
  const float* as2 = (const float*)d_in[9];
  const float* ad2 = (const float*)d_in[10];
  const float* b2  = (const float*)d_in[11];
  const float* g2  = (const float*)d_in[12];
  const float* be2 = (const float*)d_in[13];
  const float* W3  = (const float*)d_in[14];
  const float* as3 = (const float*)d_in[15];
  const float* ad3 = (const float*)d_in[16];
  const float* b3  = (const float*)d_in[17];
  const float* g3  = (const float*)d_in[18];
  const float* be3 = (const float*)d_in[19];
  const float* mW1 = (const float*)d_in[20];
  const float* mb1 = (const float*)d_in[21];
  const float* mW2 = (const float*)d_in[22];
  const float* mb2 = (const float*)d_in[23];
  const float* pW  = (const float*)d_in[24];
  const float* pb  = (const float*)d_in[25];
  const float* vW  = (const float*)d_in[26];
  const float* vb  = (const float*)d_in[27];
  float* out = (float*)d_out;

  const int TB = 256;
  const int gE   = (EE + TB - 1)/TB;
  const int gN   = (NN + TB - 1)/TB;
  const int gGrp = (NN*16 + TB - 1)/TB;   // 16-lane group per node
  const int gMlp = 1184;

  // CSR + att1 compressed; k_agg16 lands at launch index 3 for ncu capture
  k_attcount<<<gE, TB>>>(ei, x, W1, as1, ad1);   // 0
  k_scanall<<<NB1, TB>>>();                      // 1
  k_scatter<<<gE, TB>>>(ei);                     // 2

  // layer 1 (D=16, raw x, no BN)
  k_agg16<<<gGrp, TB>>>(x);                      // 3  <- profiled
  k_out<16><<<GOUT, TB>>>(W1, b1, g1, be1);      // 4

  // layer 2 (D=64, BN folded into gather)
  k_att2<<<gN, TB>>>(W2, as2, ad2);              // 5
  k_agg64<<<gGrp, TB>>>();                       // 6
  k_out<64><<<GOUT, TB>>>(W2, b2, g2, be2);      // 7

  // layer 3
  k_att2<<<gN, TB>>>(W3, as3, ad3);              // 8
  k_agg64<<<gGrp, TB>>>();                       // 9
  k_out<64><<<GOUT, TB>>>(W3, b3, g3, be3);      // 10

  // MLP + heads (fused)
  k_mlp1h<<<gMlp, TB>>>(x, mW1, mb1, mW2, mb2, pW, pb, vW, vb, out);  // 11
}